// round 13
// baseline (speedup 1.0000x reference)
#include <cuda_runtime.h>
#include <math.h>

#define SEQ       65536
#define FEAT      512
#define GEMV_BLKS 8192
#define NSEG      128
#define GRID_B    (GEMV_BLKS + NSEG)
#define TPB       256
#define THRES1    0.8f
#define THRES_UP  0.5f
#define MAXF      60

__device__ float g_a[SEQ];

// one 128B line per record; at most 2 pollers per line
struct __align__(128) SlotD { unsigned flag; float loss, cnt, lf, lv, dypre; int didx; };
struct __align__(128) Line  { unsigned v; };
__device__ SlotD g_D[NSEG];
__device__ Line  g_fA[NSEG];          // uh segment ready (epoch-tagged)
__device__ Line  g_seg[NSEG];         // g_a segment counters (monotonic)
__device__ unsigned g_epoch = 0, g_done = 0;

__device__ __forceinline__ void st_rel(unsigned* p, unsigned v) {
    asm volatile("st.release.gpu.u32 [%0], %1;" :: "l"(p), "r"(v) : "memory");
}
__device__ __forceinline__ unsigned ld_acq(const unsigned* p) {
    unsigned v;
    asm volatile("ld.acquire.gpu.u32 %0, [%1];" : "=r"(v) : "l"(p) : "memory");
    return v;
}
__device__ __forceinline__ void spin_eq(const unsigned* p, unsigned expv) {
    while (ld_acq(p) != expv) { }
}
__device__ __forceinline__ void spin_ge(const unsigned* p, unsigned tgt) {
    while (ld_acq(p) < tgt) { }
}

// OP 0: segmented max | OP 1: linear | OP 2: last-set select
// comb: t2 := t2 ∘ t1 (t1 earlier, t2 later)
template<int OP>
__device__ __forceinline__ void comb(float f1, float v1, float& f2, float& v2) {
    if (OP == 0) { v2 = (f2 != 0.f) ? fmaxf(v1, v2) : v2; f2 = f1 * f2; }
    if (OP == 1) { v2 = f2 * v1 + v2;                      f2 = f1 * f2; }
    if (OP == 2) { v2 = (f2 != 0.f) ? v1 : v2;             f2 = f1 * f2; }
}

// Block-wide EXCLUSIVE scan over 8 warps; returns exclusive prefix + total.
template<int OP>
__device__ void blk_scan_excl(float f, float v, float idv,
                              float& fex, float& vex,
                              float& ftot, float& vtot,
                              float* sf, float* sv) {
    int lane = threadIdx.x & 31, w = threadIdx.x >> 5;
#pragma unroll
    for (int d = 1; d < 32; d <<= 1) {
        float ff = __shfl_up_sync(0xffffffffu, f, d);
        float vv = __shfl_up_sync(0xffffffffu, v, d);
        if (lane >= d) comb<OP>(ff, vv, f, v);
    }
    __syncthreads();                   // protect smem reuse across calls
    if (lane == 31) { sf[w] = f; sv[w] = v; }
    __syncthreads();
    float pf = 1.f, pv = idv;
    for (int i = 0; i < w; i++) {
        float cf = sf[i], cv = sv[i];
        comb<OP>(pf, pv, cf, cv);
        pf = cf; pv = cv;
    }
    float tf = 1.f, tv = idv;
#pragma unroll
    for (int i = 0; i < 8; i++) {
        float cf = sf[i], cv = sv[i];
        comb<OP>(tf, tv, cf, cv);
        tf = cf; tv = cv;
    }
    ftot = tf; vtot = tv;
    float lf = __shfl_up_sync(0xffffffffu, f, 1);
    float lv = __shfl_up_sync(0xffffffffu, v, 1);
    if (lane == 0) { lf = 1.f; lv = idv; }
    comb<OP>(pf, pv, lf, lv);
    fex = lf; vex = lv;
}

__device__ __forceinline__ void resolve_fall(float lc, float ypre, int gidx,
                                             const float* __restrict__ th2,
                                             float& loss, float& cnt) {
    bool isneg = (lc == -1.f);
    bool nz    = (lc != 0.f);
    if (!isneg && nz) { loss += lc; cnt += 1.f; }            // * R (R=1)
    else if (!isneg && !nz && ypre >= THRES1) {
        float t2 = th2[gidx < MAXF - 1 ? gidx : MAXF - 1];
        float d = ypre - t2;
        loss += d * d; cnt += 1.f;
    }
}

// ---------------------------------------------------------------------------
// ONE kernel. Blocks 0..8191: gemv (blocks 0..127 also compute uh segment b).
// Blocks 8192..8319: scan segments, dispatched in the LAST wave.
// ---------------------------------------------------------------------------
__global__ void __launch_bounds__(TPB)
k_tgnn(const float* __restrict__ h, const float* __restrict__ W,
       const float* __restrict__ bptr,
       const float* __restrict__ up, const float* __restrict__ lab,
       const float* __restrict__ th2, float* __restrict__ out,
       int out_size) {
    __shared__ float4 sW[FEAT / 4];
    __shared__ float  sf[8], sv[8];
    __shared__ int    s_didx;
    __shared__ float  s_dypre;

    const int b    = blockIdx.x;
    const int tid  = threadIdx.x;
    const int lane = tid & 31;
    const int w    = tid >> 5;

    const unsigned e    = *(volatile unsigned*)&g_epoch;
    const unsigned expv = e + 1u;

    if (b < GEMV_BLKS) {
        // =================== GEMV block: 8 rows, 1 per warp ================
        if (tid < FEAT / 4) sW[tid] = ((const float4*)W)[tid];
        __syncthreads();
        {
            const int row = b * 8 + w;
            const float4* hr = (const float4*)(h + (size_t)row * FEAT);
            float sum = 0.f;
#pragma unroll
            for (int k = 0; k < 4; k++) {
                float4 hv = hr[lane + 32 * k];
                float4 wv = sW[lane + 32 * k];
                sum += hv.x * wv.x + hv.y * wv.y + hv.z * wv.z + hv.w * wv.w;
            }
#pragma unroll
            for (int d = 16; d; d >>= 1)
                sum += __shfl_down_sync(0xffffffffu, sum, d);
            if (lane == 0)
                g_a[row] = 1.f / (1.f + __expf(-(sum + __ldg(bptr))));
        }

        // ---- blocks 0..127: u copy + exact up_hat for segment b -----------
        if (b < NSEG) {
            const int gi2 = b * 256 + tid;           // float2 index
            float2 u2 = ((const float2*)up)[gi2];
            ((float2*)(out + 2 * SEQ))[gi2] = u2;    // u_pred copy
            float ue[2] = {u2.x, u2.y};

            float m_in = -1.f;                        // from 512-elem window
            if (b > 0) {
                float2 wu2 = ((const float2*)up)[(b - 1) * 256 + tid];
                float wf = 1.f, wv = -1.f;
#pragma unroll
                for (int ee = 0; ee < 2; ee++) {
                    float uu = (ee == 0) ? wu2.x : wu2.y;
                    if (uu >= THRES_UP) wv = fmaxf(wv, uu);
                    else { wf = 0.f; wv = -1.f; }
                }
                float fex, vex, ft, vt;
                blk_scan_excl<0>(wf, wv, -1.f, fex, vex, ft, vt, sf, sv);
                m_in = vt;                            // window total on -1
            }

            float f = 1.f, v = -1.f;
#pragma unroll
            for (int ee = 0; ee < 2; ee++) {
                if (ue[ee] >= THRES_UP) v = fmaxf(v, ue[ee]);
                else { f = 0.f; v = -1.f; }
            }
            float fexA, vexA, ftA, vtA;
            blk_scan_excl<0>(f, v, -1.f, fexA, vexA, ftA, vtA, sf, sv);
            float m = (fexA != 0.f) ? fmaxf(m_in, vexA) : vexA;

            float uh[2];
#pragma unroll
            for (int ee = 0; ee < 2; ee++) {
                if (ue[ee] >= THRES_UP) { m = fmaxf(m, ue[ee]); uh[ee] = m; }
                else                    { m = -1.f;             uh[ee] = ue[ee]; }
            }
            ((float2*)(out + 3 * SEQ))[gi2] = make_float2(uh[0], uh[1]);
        }

        __syncthreads();
        if (tid == 0) {
            __threadfence();                          // g_a + uh visible
            if (b < NSEG) st_rel(&g_fA[b].v, expv);
            atomicAdd(&g_seg[b >> 6].v, 1u);          // 64 blocks per segment
            unsigned prev = atomicAdd(&g_done, 1u);
            if (prev == (unsigned)(GRID_B - 1)) {
                g_done = 0;
                *(volatile unsigned*)&g_epoch = e + 1u;
            }
        }
        return;
    }

    // =================== scan block s: 512 elements ========================
    const int s   = b - GEMV_BLKS;
    const int gi2 = s * 256 + tid;       // float2 index

    // wait for producers (short: we dispatch in the last wave)
    if (tid == 0)            spin_ge(&g_seg[s].v, 64u * expv);
    else if (tid == 32)      { if (s > 0) spin_ge(&g_seg[s - 1].v, 64u * expv); }
    else if (tid == 64)      spin_eq(&g_fA[s].v, expv);
    else if (tid == 96)      { if (s > 0) spin_eq(&g_fA[s - 1].v, expv); }
    __syncthreads();

    const float* uh_base = out + 3 * SEQ;
    float2 uh2 = ((const float2*)uh_base)[gi2];
    float2 a2  = ((const float2*)g_a)[gi2];
    float2 l2  = ((const float2*)lab)[gi2];
    float2 wuh2 = make_float2(0.f, 0.f), wa2 = make_float2(0.f, 0.f);
    if (s > 0) {
        const int wg = (s - 1) * 256 + tid;
        wuh2 = ((const float2*)uh_base)[wg];
        wa2  = ((const float2*)g_a)[wg];
    }
    int   gbase  = gi2 * 2;
    float uhprev = (gbase == 0) ? 0.f : uh_base[gbase - 1];

    // ---- entry states from window (alpha exact-to-fp32, y exact) ----------
    float al_in = 0.f, y_in = 0.f;
    if (s > 0) {
        float wuh[2] = {wuh2.x, wuh2.y};
        float wa[2]  = {wa2.x,  wa2.y};
        float p = 1.f, q = 0.f;
#pragma unroll
        for (int ee = 0; ee < 2; ee++) {
            q = wuh[ee] * q + (1.f - wuh[ee]) * wa[ee];
            p = wuh[ee] * p;
        }
        float fexB, vexB, ftB, vtB;
        blk_scan_excl<1>(p, q, 0.f, fexB, vexB, ftB, vtB, sf, sv);
        float alw = fexB * 0.5f + vexB;      // init 0.5; error underflows
        al_in = ftB * 0.5f + vtB;
        float alwv[2];
#pragma unroll
        for (int ee = 0; ee < 2; ee++) {
            alw = wuh[ee] * alw + (1.f - wuh[ee]) * wa[ee];
            alwv[ee] = alw;
        }
        float yp = 1.f, yq = 0.f;
#pragma unroll
        for (int ee = 0; ee < 2; ee++) {
            float A = 0.f, B = 0.f;
            if (wuh[ee] >= THRES_UP) { A = 1.f - alwv[ee]; B = alwv[ee] * wuh[ee]; }
            yq = A * yq + B;
            yp = A * yp;
        }
        float fexC, vexC, ftC, vtC;
        blk_scan_excl<1>(yp, yq, 0.f, fexC, vexC, ftC, vtC, sf, sv);
        y_in = vtC;                           // exact (window has lows)
    }

    // ---- owned phase B: alpha ----------------------------------------------
    float uh[2] = {uh2.x, uh2.y};
    float ae[2] = {a2.x, a2.y};
    float p = 1.f, q = 0.f;
#pragma unroll
    for (int ee = 0; ee < 2; ee++) {
        q = uh[ee] * q + (1.f - uh[ee]) * ae[ee];
        p = uh[ee] * p;
    }
    float fexB, vexB, ftB, vtB;
    blk_scan_excl<1>(p, q, 0.f, fexB, vexB, ftB, vtB, sf, sv);
    float al = fexB * al_in + vexB;

    float alv[2];
#pragma unroll
    for (int ee = 0; ee < 2; ee++) {
        al = uh[ee] * al + (1.f - uh[ee]) * ae[ee];
        alv[ee] = al;
    }
    ((float2*)(out + SEQ))[gi2] = make_float2(alv[0], alv[1]);

    // ---- owned phase C: y ---------------------------------------------------
    float yp = 1.f, yq = 0.f;
#pragma unroll
    for (int ee = 0; ee < 2; ee++) {
        float A = 0.f, B = 0.f;
        if (uh[ee] >= THRES_UP) { A = 1.f - alv[ee]; B = alv[ee] * uh[ee]; }
        yq = A * yq + B;
        yp = A * yp;
    }
    float fexC, vexC, ftC, vtC;
    blk_scan_excl<1>(yp, yq, 0.f, fexC, vexC, ftC, vtC, sf, sv);
    float y = fexC * y_in + vexC;

    // ---- owned phase D: l_c / loss / cnt ------------------------------------
    float le[2] = {l2.x, l2.y};
    float lcf = 1.f, lcv = 0.f, loss = 0.f, cnt = 0.f;
    int   didx = -1;
    float dypre = 0.f;
    float yv[2];
    float ypre = y;
    float uprev = uhprev;                 // uh<0.5 <=> u<0.5
#pragma unroll
    for (int ee = 0; ee < 2; ee++) {
        float ynew = (uh[ee] >= THRES_UP)
                       ? (alv[ee] * uh[ee] + (1.f - alv[ee]) * ypre) : 0.f;
        yv[ee] = ynew;
        if (le[ee] >= THRES1) {
            lcv = (uh[ee] < THRES_UP) ? -1.f : (ynew - le[ee]) * (ynew - le[ee]);
            lcf = 0.f;
        }
        bool fall = (uprev >= THRES_UP) && (uh[ee] < THRES_UP);
        if (fall) {
            if (lcf == 0.f) resolve_fall(lcv, ypre, gbase + ee, th2, loss, cnt);
            else            { didx = gbase + ee; dypre = ypre; }
            lcv = 0.f; lcf = 0.f;
        }
        uprev = uh[ee];
        ypre  = ynew;
    }
    ((float2*)out)[gi2] = make_float2(yv[0], yv[1]);

    float fex2, vex2, ft2, vt2;
    blk_scan_excl<2>(lcf, lcv, 0.f, fex2, vex2, ft2, vt2, sf, sv);
    if (didx >= 0 && fex2 == 0.f) {
        resolve_fall(vex2, dypre, didx, th2, loss, cnt);
        didx = -1;
    }
    if (tid == 0) { s_didx = -1; s_dypre = 0.f; }
    __syncthreads();
    if (didx >= 0) { s_didx = didx; s_dypre = dypre; }   // at most one thread
    __syncthreads();

#pragma unroll
    for (int d = 16; d; d >>= 1) {
        loss += __shfl_down_sync(0xffffffffu, loss, d);
        cnt  += __shfl_down_sync(0xffffffffu, cnt,  d);
    }
    if (lane == 0) { sf[w] = loss; sv[w] = cnt; }
    __syncthreads();
    if (tid == 0) {
        float L = 0.f, C = 0.f;
#pragma unroll
        for (int i = 0; i < 8; i++) { L += sf[i]; C += sv[i]; }
        SlotD* d = &g_D[s];
        d->loss = L; d->cnt = C; d->lf = ft2; d->lv = vt2;
        d->didx = s_didx; d->dypre = s_dypre;
        st_rel(&d->flag, expv);
    }
    __syncthreads();

    // ---- ONLY exchange: scan block 0 gathers all D records ------------------
    if (s == 0) {
        float L = 0.f, C = 0.f, fl = 1.f, vl = 0.f;
        int   di = -1;
        float dy = 0.f;
        if (tid < NSEG) {
            spin_eq(&g_D[tid].flag, expv);     // 1 poller per line
            SlotD* d = &g_D[tid];
            L = d->loss; C = d->cnt; fl = d->lf; vl = d->lv;
            di = d->didx; dy = d->dypre;
#pragma unroll
            for (int dd = 1; dd < 32; dd <<= 1) {
                float ff = __shfl_up_sync(0xffffffffu, fl, dd);
                float vv = __shfl_up_sync(0xffffffffu, vl, dd);
                if (lane >= dd) comb<2>(ff, vv, fl, vl);
            }
        }
        __syncthreads();
        if (tid < NSEG && lane == 31) { sf[w] = fl; sv[w] = vl; }
        __syncthreads();
        if (tid < NSEG) {
            float pf = 1.f, pv = 0.f;
            for (int i = 0; i < w; i++) {
                float cf = sf[i], cv = sv[i];
                comb<2>(pf, pv, cf, cv);
                pf = cf; pv = cv;
            }
            float lf = __shfl_up_sync(0xffffffffu, fl, 1);
            float lvv = __shfl_up_sync(0xffffffffu, vl, 1);
            if (lane == 0) { lf = 1.f; lvv = 0.f; }
            comb<2>(pf, pv, lf, lvv);
            float lc_in = (lf != 0.f) ? 0.f : lvv;    // initial l_c = 0
            if (di >= 0) resolve_fall(lc_in, dy, di, th2, L, C);
#pragma unroll
            for (int d2 = 16; d2; d2 >>= 1) {
                L += __shfl_down_sync(0xffffffffu, L, d2);
                C += __shfl_down_sync(0xffffffffu, C, d2);
            }
        }
        __syncthreads();
        if (tid < NSEG && lane == 0) { sf[w] = L; sv[w] = C; }
        __syncthreads();
        if (tid == 0 && out_size >= 4 * SEQ + 2) {
            out[4 * SEQ]     = sf[0] + sf[1] + sf[2] + sf[3];
            out[4 * SEQ + 1] = sv[0] + sv[1] + sv[2] + sv[3];
        }
    }

    // ---- epoch bookkeeping ---------------------------------------------------
    __syncthreads();
    if (tid == 0) {
        unsigned prev = atomicAdd(&g_done, 1u);
        if (prev == (unsigned)(GRID_B - 1)) {
            g_done = 0;
            *(volatile unsigned*)&g_epoch = e + 1u;
        }
    }
}

// ---------------------------------------------------------------------------
extern "C" void kernel_launch(void* const* d_in, const int* in_sizes, int n_in,
                              void* d_out, int out_size) {
    const float* h      = (const float*)d_in[0];
    const float* W      = (const float*)d_in[1];
    const float* bptr   = (const float*)d_in[2];
    // d_in[3] = u (unused in outputs/loss)
    const float* u_pred = (const float*)d_in[4];
    const float* label  = (const float*)d_in[5];
    const float* thres2 = (const float*)d_in[6];
    float* out = (float*)d_out;

    k_tgnn<<<GRID_B, TPB>>>(h, W, bptr, u_pred, label, thres2, out, out_size);
}

// round 14
// speedup vs baseline: 1.1754x; 1.1754x over previous
#include <cuda_runtime.h>
#include <math.h>

#define SEQ      65536
#define FEAT     512
#define NB       128          // scan segments / scan blocks
#define TPB      256          // scan kernel threads (128 window + 128 owned)
#define THRES1   0.8f
#define THRES_UP 0.5f
#define MAXF     60

__device__ float g_a[SEQ];

// one 128B line per record; exactly one poller per line
struct __align__(128) SlotD { unsigned flag; float loss, cnt, lf, lv, dypre; int didx; };
__device__ SlotD g_D[NB];
__device__ unsigned g_epoch = 0, g_done = 0;

__device__ __forceinline__ void st_rel(unsigned* p, unsigned v) {
    asm volatile("st.release.gpu.u32 [%0], %1;" :: "l"(p), "r"(v) : "memory");
}
__device__ __forceinline__ unsigned ld_acq(const unsigned* p) {
    unsigned v;
    asm volatile("ld.acquire.gpu.u32 %0, [%1];" : "=r"(v) : "l"(p) : "memory");
    return v;
}
__device__ __forceinline__ void spin_eq(const unsigned* p, unsigned expv) {
    while (ld_acq(p) != expv) { }
}

// OP 0: segmented max | OP 1: linear | OP 2: last-set select
// comb: t2 := t2 ∘ t1 (t1 earlier, t2 later)
template<int OP>
__device__ __forceinline__ void comb(float f1, float v1, float& f2, float& v2) {
    if (OP == 0) { v2 = (f2 != 0.f) ? fmaxf(v1, v2) : v2; f2 = f1 * f2; }
    if (OP == 1) { v2 = f2 * v1 + v2;                      f2 = f1 * f2; }
    if (OP == 2) { v2 = (f2 != 0.f) ? v1 : v2;             f2 = f1 * f2; }
}

// Block-wide EXCLUSIVE scan over NWARPS warps; exclusive prefix + total.
template<int OP, int NWARPS>
__device__ void blk_scan_excl(float f, float v, float idv,
                              float& fex, float& vex,
                              float& ftot, float& vtot,
                              float* sf, float* sv) {
    int lane = threadIdx.x & 31, w = threadIdx.x >> 5;
#pragma unroll
    for (int d = 1; d < 32; d <<= 1) {
        float ff = __shfl_up_sync(0xffffffffu, f, d);
        float vv = __shfl_up_sync(0xffffffffu, v, d);
        if (lane >= d) comb<OP>(ff, vv, f, v);
    }
    __syncthreads();                   // protect smem reuse across calls
    if (lane == 31) { sf[w] = f; sv[w] = v; }
    __syncthreads();
    float pf = 1.f, pv = idv;
    for (int i = 0; i < w; i++) {
        float cf = sf[i], cv = sv[i];
        comb<OP>(pf, pv, cf, cv);
        pf = cf; pv = cv;
    }
    float tf = 1.f, tv = idv;
#pragma unroll
    for (int i = 0; i < NWARPS; i++) {
        float cf = sf[i], cv = sv[i];
        comb<OP>(tf, tv, cf, cv);
        tf = cf; tv = cv;
    }
    ftot = tf; vtot = tv;
    float lf = __shfl_up_sync(0xffffffffu, f, 1);
    float lv = __shfl_up_sync(0xffffffffu, v, 1);
    if (lane == 0) { lf = 1.f; lv = idv; }
    comb<OP>(pf, pv, lf, lv);
    fex = lf; vex = lv;
}

__device__ __forceinline__ void resolve_fall(float lc, float ypre, int gidx,
                                             const float* __restrict__ th2,
                                             float& loss, float& cnt) {
    bool isneg = (lc == -1.f);
    bool nz    = (lc != 0.f);
    if (!isneg && nz) { loss += lc; cnt += 1.f; }            // * R (R=1)
    else if (!isneg && !nz && ypre >= THRES1) {
        float t2 = th2[gidx < MAXF - 1 ? gidx : MAXF - 1];
        float d = ypre - t2;
        loss += d * d; cnt += 1.f;
    }
}

// ---------------------------------------------------------------------------
// Kernel 1: GEMV + sigmoid (HBM-bound, 8192 blocks). Blocks 0..127 ALSO do
// the u_pred-only work for scan segment b: u copy + exact up_hat.
// ---------------------------------------------------------------------------
__global__ void __launch_bounds__(256)
gemv_sigmoid_kernel(const float* __restrict__ h,
                    const float* __restrict__ W,
                    const float* __restrict__ bptr,
                    const float* __restrict__ up,
                    float* __restrict__ out) {
    __shared__ float4 sW[FEAT / 4];
    __shared__ float  sf[8], sv[8];
    const int tid = threadIdx.x, lane = tid & 31, w = tid >> 5;
    const int b   = blockIdx.x;

    if (tid < FEAT / 4) sW[tid] = ((const float4*)W)[tid];
    __syncthreads();

    // ---- gemv: 8 rows per block, 1 per warp -------------------------------
    {
        const int row = b * 8 + w;
        const float4* hr = (const float4*)(h + (size_t)row * FEAT);
        float sum = 0.f;
#pragma unroll
        for (int k = 0; k < 4; k++) {
            float4 hv = hr[lane + 32 * k];
            float4 wv = sW[lane + 32 * k];
            sum += hv.x * wv.x + hv.y * wv.y + hv.z * wv.z + hv.w * wv.w;
        }
#pragma unroll
        for (int d = 16; d; d >>= 1) sum += __shfl_down_sync(0xffffffffu, sum, d);
        if (lane == 0) g_a[row] = 1.f / (1.f + __expf(-(sum + __ldg(bptr))));
    }

    // ---- extra: u-only scan work for segment b (blocks 0..127) ------------
    if (b < NB) {
        const int gi2 = b * 256 + tid;           // float2 index in segment
        float2 u2 = ((const float2*)up)[gi2];
        ((float2*)(out + 2 * SEQ))[gi2] = u2;    // u_pred copy output
        float ue[2] = {u2.x, u2.y};

        float m_in = -1.f;                        // exact from 512-elem window
        if (b > 0) {
            float2 wu2 = ((const float2*)up)[(b - 1) * 256 + tid];
            float wf = 1.f, wv = -1.f;
#pragma unroll
            for (int ee = 0; ee < 2; ee++) {
                float uu = (ee == 0) ? wu2.x : wu2.y;
                if (uu >= THRES_UP) wv = fmaxf(wv, uu);
                else { wf = 0.f; wv = -1.f; }
            }
            float fex, vex, ft, vt;
            blk_scan_excl<0, 8>(wf, wv, -1.f, fex, vex, ft, vt, sf, sv);
            m_in = vt;                            // window total applied to -1
        }

        float f = 1.f, v = -1.f;
#pragma unroll
        for (int ee = 0; ee < 2; ee++) {
            if (ue[ee] >= THRES_UP) v = fmaxf(v, ue[ee]);
            else { f = 0.f; v = -1.f; }
        }
        float fexA, vexA, ftA, vtA;
        blk_scan_excl<0, 8>(f, v, -1.f, fexA, vexA, ftA, vtA, sf, sv);
        float m = (fexA != 0.f) ? fmaxf(m_in, vexA) : vexA;

        float uh[2];
#pragma unroll
        for (int ee = 0; ee < 2; ee++) {
            if (ue[ee] >= THRES_UP) { m = fmaxf(m, ue[ee]); uh[ee] = m; }
            else                    { m = -1.f;             uh[ee] = ue[ee]; }
        }
        ((float2*)(out + 3 * SEQ))[gi2] = make_float2(uh[0], uh[1]);
    }
}

// ---------------------------------------------------------------------------
// Kernel 2: fused window+owned scans. Threads 0..127 carry the 512-element
// lookback window, threads 128..255 the owned 512-element segment — ONE
// block scan serves both. Single exchange: final loss gather.
// ---------------------------------------------------------------------------
__global__ void __launch_bounds__(TPB, 1)
k_scan_fused(const float* __restrict__ lab, const float* __restrict__ th2,
             float* __restrict__ out, int out_size) {
    __shared__ float sf[8], sv[8];
    __shared__ float s_last[TPB];
    __shared__ int   s_didx;
    __shared__ float s_dypre;

    const int b    = blockIdx.x;
    const int tid  = threadIdx.x;
    const int lane = tid & 31;
    const int w    = tid >> 5;
    const bool owned = (tid >= 128);
    const bool have_win = (b > 0);

    const unsigned e    = *(volatile unsigned*)&g_epoch;
    const unsigned expv = e + 1u;

    // float4 index: window threads -> segment b-1, owned threads -> segment b
    const int gi = owned ? (b * 128 + (tid - 128)) : ((b - 1) * 128 + tid);
    const bool active = owned || have_win;

    const float* uh_base = out + 3 * SEQ;
    float4 uh4 = make_float4(0.f, 0.f, 0.f, 0.f);
    float4 a4  = make_float4(0.f, 0.f, 0.f, 0.f);
    float4 l4  = make_float4(0.f, 0.f, 0.f, 0.f);
    if (active) {
        uh4 = ((const float4*)uh_base)[gi];
        a4  = ((const float4*)g_a)[gi];
        if (owned) l4 = ((const float4*)lab)[gi];
    }
    float uh[4] = {uh4.x, uh4.y, uh4.z, uh4.w};
    float ae[4] = {a4.x, a4.y, a4.z, a4.w};

    s_last[tid] = active ? uh[3] : 0.f;          // last uh of this chunk

    // ================= Fused phase B: alpha over window+owned ==============
    float p = 1.f, q = 0.f;
    if (active) {
#pragma unroll
        for (int ee = 0; ee < 4; ee++) {
            q = uh[ee] * q + (1.f - uh[ee]) * ae[ee];
            p = uh[ee] * p;
        }
    }
    float fexB, vexB, ftB, vtB;
    blk_scan_excl<1, 8>(p, q, 0.f, fexB, vexB, ftB, vtB, sf, sv);
    const float al_init = have_win ? 0.5f : 0.f; // init err underflows to 0
    float al = fexB * al_init + vexB;

    float alv[4];
#pragma unroll
    for (int ee = 0; ee < 4; ee++) {
        al = uh[ee] * al + (1.f - uh[ee]) * ae[ee];
        alv[ee] = al;
    }
    if (owned)
        ((float4*)(out + SEQ))[gi] = make_float4(alv[0], alv[1], alv[2], alv[3]);

    // ================= Fused phase C: y over window+owned ==================
    float yp = 1.f, yq = 0.f;
    if (active) {
#pragma unroll
        for (int ee = 0; ee < 4; ee++) {
            float A = 0.f, B = 0.f;
            if (uh[ee] >= THRES_UP) { A = 1.f - alv[ee]; B = alv[ee] * uh[ee]; }
            yq = A * yq + B;
            yp = A * yp;
        }
    }
    float fexC, vexC, ftC, vtC;
    blk_scan_excl<1, 8>(yp, yq, 0.f, fexC, vexC, ftC, vtC, sf, sv);
    float y = vexC;                              // init y = 0 (exact)

    // ================= Phase D (owned threads): l_c / loss / cnt ===========
    float le[4] = {l4.x, l4.y, l4.z, l4.w};
    float lcf = 1.f, lcv = 0.f, loss = 0.f, cnt = 0.f;
    int   didx = -1;
    float dypre = 0.f;
    if (owned) {
        int   gbase = gi * 4;
        float uprev = (tid == 128 && b == 0) ? 0.f : s_last[tid - 1];
        float yv[4];
        float ypre = y;
#pragma unroll
        for (int ee = 0; ee < 4; ee++) {
            float ynew = (uh[ee] >= THRES_UP)
                           ? (alv[ee] * uh[ee] + (1.f - alv[ee]) * ypre) : 0.f;
            yv[ee] = ynew;
            if (le[ee] >= THRES1) {
                lcv = (uh[ee] < THRES_UP) ? -1.f
                                          : (ynew - le[ee]) * (ynew - le[ee]);
                lcf = 0.f;
            }
            bool fall = (uprev >= THRES_UP) && (uh[ee] < THRES_UP);
            if (fall) {
                if (lcf == 0.f) resolve_fall(lcv, ypre, gbase + ee, th2, loss, cnt);
                else            { didx = gbase + ee; dypre = ypre; }
                lcv = 0.f; lcf = 0.f;
            }
            uprev = uh[ee];
            ypre  = ynew;
        }
        ((float4*)out)[gi] = make_float4(yv[0], yv[1], yv[2], yv[3]);
    }

    // l_c scan (window threads = identity); resolve in-block defers
    float fex2, vex2, ft2, vt2;
    blk_scan_excl<2, 8>(lcf, lcv, 0.f, fex2, vex2, ft2, vt2, sf, sv);
    if (didx >= 0 && fex2 == 0.f) {
        resolve_fall(vex2, dypre, didx, th2, loss, cnt);
        didx = -1;
    }
    if (tid == 0) { s_didx = -1; s_dypre = 0.f; }
    __syncthreads();
    if (didx >= 0) { s_didx = didx; s_dypre = dypre; }   // at most one thread
    __syncthreads();

    // block loss/cnt sums (8 warps; window warps contribute 0)
#pragma unroll
    for (int d = 16; d; d >>= 1) {
        loss += __shfl_down_sync(0xffffffffu, loss, d);
        cnt  += __shfl_down_sync(0xffffffffu, cnt,  d);
    }
    if (lane == 0) { sf[w] = loss; sv[w] = cnt; }
    __syncthreads();
    if (tid == 0) {
        float L = 0.f, C = 0.f;
#pragma unroll
        for (int i = 0; i < 8; i++) { L += sf[i]; C += sv[i]; }
        SlotD* d = &g_D[b];
        d->loss = L; d->cnt = C; d->lf = ft2; d->lv = vt2;
        d->didx = s_didx; d->dypre = s_dypre;
        st_rel(&d->flag, expv);
    }
    __syncthreads();

    // ============ ONLY exchange: block 0 gathers all D records =============
    if (b == 0) {
        float L = 0.f, C = 0.f, fl = 1.f, vl = 0.f;
        int   di = -1;
        float dy = 0.f;
        if (tid < NB) {
            spin_eq(&g_D[tid].flag, expv);       // 1 poller per line
            SlotD* d = &g_D[tid];
            L = d->loss; C = d->cnt; fl = d->lf; vl = d->lv;
            di = d->didx; dy = d->dypre;
#pragma unroll
            for (int dd = 1; dd < 32; dd <<= 1) {
                float ff = __shfl_up_sync(0xffffffffu, fl, dd);
                float vv = __shfl_up_sync(0xffffffffu, vl, dd);
                if (lane >= dd) comb<2>(ff, vv, fl, vl);
            }
        }
        __syncthreads();
        if (tid < NB && lane == 31) { sf[w] = fl; sv[w] = vl; }
        __syncthreads();
        if (tid < NB) {
            float pf = 1.f, pv = 0.f;
            for (int i = 0; i < w; i++) {
                float cf = sf[i], cv = sv[i];
                comb<2>(pf, pv, cf, cv);
                pf = cf; pv = cv;
            }
            float lf = __shfl_up_sync(0xffffffffu, fl, 1);
            float lvv = __shfl_up_sync(0xffffffffu, vl, 1);
            if (lane == 0) { lf = 1.f; lvv = 0.f; }
            comb<2>(pf, pv, lf, lvv);
            float lc_in = (lf != 0.f) ? 0.f : lvv;    // initial l_c = 0
            if (di >= 0) resolve_fall(lc_in, dy, di, th2, L, C);
#pragma unroll
            for (int d2 = 16; d2; d2 >>= 1) {
                L += __shfl_down_sync(0xffffffffu, L, d2);
                C += __shfl_down_sync(0xffffffffu, C, d2);
            }
        }
        __syncthreads();
        if (tid < NB && lane == 0) { sf[w] = L; sv[w] = C; }
        __syncthreads();
        if (tid == 0 && out_size >= 4 * SEQ + 2) {
            out[4 * SEQ]     = sf[0] + sf[1] + sf[2] + sf[3];
            out[4 * SEQ + 1] = sv[0] + sv[1] + sv[2] + sv[3];
        }
    }

    // ============ Epoch advance (graph-replay safe, no resets) =============
    __syncthreads();
    if (tid == 0) {
        unsigned prev = atomicAdd(&g_done, 1u);
        if (prev == (unsigned)(NB - 1)) {
            g_done = 0;
            *(volatile unsigned*)&g_epoch = e + 1u;
        }
    }
}

// ---------------------------------------------------------------------------
extern "C" void kernel_launch(void* const* d_in, const int* in_sizes, int n_in,
                              void* d_out, int out_size) {
    const float* h      = (const float*)d_in[0];
    const float* W      = (const float*)d_in[1];
    const float* bptr   = (const float*)d_in[2];
    // d_in[3] = u (unused in outputs/loss)
    const float* u_pred = (const float*)d_in[4];
    const float* label  = (const float*)d_in[5];
    const float* thres2 = (const float*)d_in[6];
    float* out = (float*)d_out;

    gemv_sigmoid_kernel<<<SEQ / 8, 256>>>(h, W, bptr, u_pred, out);
    k_scan_fused<<<NB, TPB>>>(label, thres2, out, out_size);
}